// round 13
// baseline (speedup 1.0000x reference)
#include <cuda_runtime.h>
#include <cstdint>

// Fixed shape: stimuli [4,32,304,608,1] fp32, eye [4,32,2,3]
constexpr int H  = 304;
constexpr int W  = 608;
constexpr int HW = H * W;
constexpr int NFRAMES = 128;

constexpr int WARPS_PER_FRAME = HW / (32 * 4);     // 1444 (4 px per thread)
constexpr int WARPS_PER_BLOCK = 4;                 // 128 threads
constexpr int BLOCKS_X = WARPS_PER_FRAME / WARPS_PER_BLOCK;  // 361
constexpr int ITERS = 4;

__global__ __launch_bounds__(WARPS_PER_BLOCK * 32) void warp_bilinear_kernel(
    const float* __restrict__ stimuli,
    const float* __restrict__ eye,
    float* __restrict__ out)
{
    const int n    = blockIdx.y;
    const int wi   = blockIdx.x * WARPS_PER_BLOCK + (threadIdx.x >> 5);  // 0..1443
    const int lane = threadIdx.x & 31;

    const float* a = eye + (size_t)n * 6;
    const float a00 = __ldg(a + 0);
    const float a01 = __ldg(a + 1);
    const float a02 = __ldg(a + 2);
    const float a10 = __ldg(a + 3);
    const float a11 = __ldg(a + 4);
    const float a12 = __ldg(a + 5);

    // ---- Per-frame warp-tile shape selection (block-uniform) ----
    // Shapes s=0..4: c=32>>s cols, r=1<<s rows per warp-iteration.
    // s<3: iterate 4x along y (tile c x 4r); s>=3: iterate 4x along x (4c x r).
    // Cost model: 4 gather LDGs x lines-per-LDG + r store wavefronts.
    const float A00 = fabsf(a00), A01 = fabsf(a01);
    const float A10 = fabsf(a10), A11 = fabsf(a11);
    int s = 0;
    {
        float best = 3.402823e38f;
#pragma unroll
        for (int k = 0; k < 5; ++k) {
            const float cf = (float)(32 >> k);
            const float rf = (float)(1 << k);
            const float ylines = 0.5f * A10 * cf + A11 * rf + 1.0f;
            const float xfrac  = 1.0f + (A00 * cf + 0.5f * A01 * rf) * (1.0f / 32.0f);
            const float f = 4.0f * ylines * xfrac + rf;
            if (f < best) { best = f; s = k; }
        }
    }

    const int c      = 32 >> s;          // cols per warp row
    const int r      = 1 << s;           // rows per warp
    const int log2c  = 5 - s;
    const bool xIter = (s >= 3);
    const int tileW  = xIter ? (c << 2) : c;
    const int tileH  = xIter ? (r << 2) >> 2 : (r << 2);   // xIter ? r : 4r
    const int log2W  = xIter ? (log2c + 2) : log2c;        // log2(tileW)
    const int TX     = 19 << (5 - log2W);                  // 608 / tileW

    const int tx = wi % TX;
    const int ty = wi / TX;

    const int col0 = tx * tileW + (lane & (c - 1));
    const int row0 = ty * tileH + (lane >> log2c);
    const int colStep = xIter ? c : 0;
    const int rowStep = xIter ? 0 : r;

    // jnp.linspace(-1,1,n): v[i] = fl(-1 + fl(i*step)), endpoint exactly 1.0
    const float step_x = 2.0f / (float)(W - 1);
    const float step_y = 2.0f / (float)(H - 1);

    const float* __restrict__ img = stimuli + (size_t)n * HW;
    float* __restrict__       dst = out     + (size_t)n * HW;

#pragma unroll
    for (int i = 0; i < ITERS; ++i) {
        const int col = col0 + i * colStep;
        const int row = row0 + i * rowStep;

        const float xt = (col == W - 1) ? 1.0f
                       : __fadd_rn(-1.0f, __fmul_rn((float)col, step_x));
        const float yt = (row == H - 1) ? 1.0f
                       : __fadd_rn(-1.0f, __fmul_rn((float)row, step_y));

        // einsum k-order fmuladd chain: T = fadd(fmaf(a1, yt, fmul(a0, xt)), a2)
        const float Tx = __fadd_rn(__fmaf_rn(a01, yt, __fmul_rn(a00, xt)), a02);
        const float Ty = __fadd_rn(__fmaf_rn(a11, yt, __fmul_rn(a10, xt)), a12);

        const float x = __fmul_rn(__fadd_rn(Tx, 1.0f), (float)W * 0.5f);
        const float y = __fmul_rn(__fadd_rn(Ty, 1.0f), (float)H * 0.5f);

        const int x0u = (int)floorf(x);
        const int y0u = (int)floorf(y);
        const int x0 = min(max(x0u, 0), W - 1);
        const int x1 = min(max(x0u + 1, 0), W - 1);
        const int y0 = min(max(y0u, 0), H - 1);
        const int y1 = min(max(y0u + 1, 0), H - 1);

        const int dx  = x1 - x0;          // 0 or 1
        const int dyW = (y1 - y0) * W;    // 0 or W
        const float* pA = img + y0 * W + x0;

        const float Ia = __ldg(pA);
        const float Ic = __ldg(pA + dx);
        const float Ib = __ldg(pA + dyW);
        const float Id = __ldg(pA + dyW + dx);

        const float x0f = (float)x0, x1f = (float)x1;
        const float y0f = (float)y0, y1f = (float)y1;

        // separately rounded subs/muls (no fma contraction) — matches JAX
        const float dx1 = __fsub_rn(x1f, x);
        const float dx0 = __fsub_rn(x, x0f);
        const float dy1 = __fsub_rn(y1f, y);
        const float dy0 = __fsub_rn(y, y0f);

        const float wa = __fmul_rn(dx1, dy1);
        const float wb = __fmul_rn(dx1, dy0);
        const float wc = __fmul_rn(dx0, dy1);
        const float wd = __fmul_rn(dx0, dy0);

        const float p1 = __fmul_rn(wa, Ia);
        const float p2 = __fmul_rn(wb, Ib);
        const float p3 = __fmul_rn(wc, Ic);
        const float p4 = __fmul_rn(wd, Id);
        dst[row * W + col] = __fadd_rn(__fadd_rn(__fadd_rn(p1, p2), p3), p4);
    }
}

extern "C" void kernel_launch(void* const* d_in, const int* in_sizes, int n_in,
                              void* d_out, int out_size)
{
    const float* stimuli = (const float*)d_in[0];
    const float* eye     = (const float*)d_in[1];
    float* out           = (float*)d_out;

    dim3 block(WARPS_PER_BLOCK * 32);
    dim3 grid(BLOCKS_X, NFRAMES);
    warp_bilinear_kernel<<<grid, block>>>(stimuli, eye, out);
}

// round 14
// speedup vs baseline: 1.3638x; 1.3638x over previous
#include <cuda_runtime.h>
#include <cstdint>

// Fixed shape: stimuli [4,32,304,608,1] fp32, eye [4,32,2,3]
constexpr int H  = 304;
constexpr int W  = 608;
constexpr int HW = H * W;
constexpr int NFRAMES = 128;

// Warp output tile: 8 cols x 4 rows per iteration, 4 iterations (8x16 px).
// Measured optimal across {32x1, 16x2, 8x4, 4x8, 2x16} and adaptive variants.
constexpr int TCOLS = 8;
constexpr int TROWS = 4;
constexpr int ITERS = 4;
constexpr int COL_TILES = W / TCOLS;               // 76
constexpr int ROW_TILES = H / (TROWS * ITERS);     // 19
constexpr int WARPS_PER_FRAME = COL_TILES * ROW_TILES;  // 1444
constexpr int WARPS_PER_BLOCK = 4;                 // 128 threads
constexpr int BLOCKS_X = WARPS_PER_FRAME / WARPS_PER_BLOCK;  // 361

__global__ __launch_bounds__(WARPS_PER_BLOCK * 32) void warp_bilinear_kernel(
    const float* __restrict__ stimuli,
    const float* __restrict__ eye,
    float* __restrict__ out)
{
    const int n    = blockIdx.y;
    const int warp = blockIdx.x * WARPS_PER_BLOCK + (threadIdx.x >> 5);
    const int lane = threadIdx.x & 31;

    const int rt = warp / COL_TILES;                // row tile 0..18
    const int ct = warp - rt * COL_TILES;           // col tile 0..75

    const int col   = ct * TCOLS + (lane & (TCOLS - 1));
    const int rbase = rt * (TROWS * ITERS) + (lane >> 3);

    const float* a = eye + (size_t)n * 6;
    const float a00 = __ldg(a + 0);
    const float a01 = __ldg(a + 1);
    const float a02 = __ldg(a + 2);
    const float a10 = __ldg(a + 3);
    const float a11 = __ldg(a + 4);
    const float a12 = __ldg(a + 5);

    // jnp.linspace(-1,1,n): v[i] = fl(-1 + fl(i*step)), endpoint exactly 1.0
    const float step_x = 2.0f / (float)(W - 1);
    const float step_y = 2.0f / (float)(H - 1);
    const float xt = (col == W - 1) ? 1.0f
                   : __fadd_rn(-1.0f, __fmul_rn((float)col, step_x));

    const float a00xt = __fmul_rn(a00, xt);
    const float a10xt = __fmul_rn(a10, xt);

    const float* __restrict__ img = stimuli + (size_t)n * HW;
    float* pOut = out + (size_t)n * HW + rbase * W + col;  // strength-reduced

#pragma unroll
    for (int i = 0; i < ITERS; ++i) {
        const int row = rbase + i * TROWS;
        const float yt = (row == H - 1) ? 1.0f
                       : __fadd_rn(-1.0f, __fmul_rn((float)row, step_y));

        // einsum k-order fmuladd chain: T = fadd(fmaf(a1, yt, a0*xt), a2)
        const float Tx = __fadd_rn(__fmaf_rn(a01, yt, a00xt), a02);
        const float Ty = __fadd_rn(__fmaf_rn(a11, yt, a10xt), a12);

        const float x = __fmul_rn(__fadd_rn(Tx, 1.0f), (float)W * 0.5f);
        const float y = __fmul_rn(__fadd_rn(Ty, 1.0f), (float)H * 0.5f);

        // single-instruction floor-converts (F2I.S32.F32.FLOOR)
        const int x0u = __float2int_rd(x);
        const int y0u = __float2int_rd(y);
        const int x0 = min(max(x0u, 0), W - 1);
        const int x1 = min(max(x0u + 1, 0), W - 1);
        const int y0 = min(max(y0u, 0), H - 1);
        const int y1 = min(max(y0u + 1, 0), H - 1);

        // Single address chain + small offsets (dx in {0,1}, dyW in {0,W})
        const int dx  = x1 - x0;
        const int dyW = (y1 - y0) * W;
        const float* pA = img + y0 * W + x0;

        // row-paired issue order
        const float Ia = __ldg(pA);
        const float Ic = __ldg(pA + dx);
        const float Ib = __ldg(pA + dyW);
        const float Id = __ldg(pA + dyW + dx);

        const float x0f = (float)x0, x1f = (float)x1;
        const float y0f = (float)y0, y1f = (float)y1;

        // separately rounded subs/muls (no fma contraction) — matches JAX
        const float dx1 = __fsub_rn(x1f, x);
        const float dx0 = __fsub_rn(x, x0f);
        const float dy1 = __fsub_rn(y1f, y);
        const float dy0 = __fsub_rn(y, y0f);

        const float wa = __fmul_rn(dx1, dy1);
        const float wb = __fmul_rn(dx1, dy0);
        const float wc = __fmul_rn(dx0, dy1);
        const float wd = __fmul_rn(dx0, dy0);

        const float p1 = __fmul_rn(wa, Ia);
        const float p2 = __fmul_rn(wb, Ib);
        const float p3 = __fmul_rn(wc, Ic);
        const float p4 = __fmul_rn(wd, Id);
        *pOut = __fadd_rn(__fadd_rn(__fadd_rn(p1, p2), p3), p4);

        pOut += TROWS * W;   // constant increment instead of per-iter IMAD
    }
}

extern "C" void kernel_launch(void* const* d_in, const int* in_sizes, int n_in,
                              void* d_out, int out_size)
{
    const float* stimuli = (const float*)d_in[0];
    const float* eye     = (const float*)d_in[1];
    float* out           = (float*)d_out;

    dim3 block(WARPS_PER_BLOCK * 32);
    dim3 grid(BLOCKS_X, NFRAMES);
    warp_bilinear_kernel<<<grid, block>>>(stimuli, eye, out);
}